// round 1
// baseline (speedup 1.0000x reference)
#include <cuda_runtime.h>
#include <math.h>

// ---------------------------------------------------------------------------
// PositionEvaluator: fused gated-vector MLP chain.
// One CTA processes R=16 focal rows end-to-end. All activations live in
// shared memory transposed [channel][row] (row fast -> conflict-free LDS,
// weight broadcast across the 16 row-lanes of each warp-half).
// Weights are read via __ldg float4; each element is touched once per CTA.
// ---------------------------------------------------------------------------

#define R  16          // rows per CTA
#define G  16          // channel groups (threads per output-slice)
#define NT 256         // threads per CTA

struct SM {
  float sv[3][256][R];    // current vector activations (comp, channel, row)
  float sh[3][256][R];    // vh / d scratch
  float snorm[256][R];    // ||vh|| per channel
  float ssc[256][R];      // scalar activations (s / s2 concat parts)
  float so[128][R];       // out_s (pre-activation) ; reused for final reduce
  float rp[3][R];         // relpos
  int   nidx[R];          // gathered node index
};

// y[i][o][r] = sum_c W[o][c] * x[i][c][r];  optionally nrm[o][r] = ||y[.][o][r]||
template<int OUT, int CIN, bool NORM>
__device__ __forceinline__ void matvec_v(const float* __restrict__ W,
                                         float (*x)[256][R],
                                         float (*y)[256][R],
                                         float (*nrm)[R],
                                         int g, int r)
{
  constexpr int J = OUT / G;
  float acc[J][3];
#pragma unroll
  for (int j = 0; j < J; ++j) { acc[j][0] = 0.f; acc[j][1] = 0.f; acc[j][2] = 0.f; }
#pragma unroll 1
  for (int c = 0; c < CIN; c += 4) {
    float xv[3][4];
#pragma unroll
    for (int cc = 0; cc < 4; ++cc) {
      xv[0][cc] = x[0][c + cc][r];
      xv[1][cc] = x[1][c + cc][r];
      xv[2][cc] = x[2][c + cc][r];
    }
#pragma unroll
    for (int j = 0; j < J; ++j) {
      const int o = g + G * j;
      const float4 w = __ldg(reinterpret_cast<const float4*>(W + (size_t)o * CIN + c));
      acc[j][0] = fmaf(w.x, xv[0][0], acc[j][0]);
      acc[j][1] = fmaf(w.x, xv[1][0], acc[j][1]);
      acc[j][2] = fmaf(w.x, xv[2][0], acc[j][2]);
      acc[j][0] = fmaf(w.y, xv[0][1], acc[j][0]);
      acc[j][1] = fmaf(w.y, xv[1][1], acc[j][1]);
      acc[j][2] = fmaf(w.y, xv[2][1], acc[j][2]);
      acc[j][0] = fmaf(w.z, xv[0][2], acc[j][0]);
      acc[j][1] = fmaf(w.z, xv[1][2], acc[j][1]);
      acc[j][2] = fmaf(w.z, xv[2][2], acc[j][2]);
      acc[j][0] = fmaf(w.w, xv[0][3], acc[j][0]);
      acc[j][1] = fmaf(w.w, xv[1][3], acc[j][1]);
      acc[j][2] = fmaf(w.w, xv[2][3], acc[j][2]);
    }
  }
#pragma unroll
  for (int j = 0; j < J; ++j) {
    const int o = g + G * j;
    y[0][o][r] = acc[j][0];
    y[1][o][r] = acc[j][1];
    y[2][o][r] = acc[j][2];
    if (NORM)
      nrm[o][r] = sqrtf(acc[j][0] * acc[j][0] + acc[j][1] * acc[j][1] + acc[j][2] * acc[j][2]);
  }
}

// y[o][r] = sum_{k<K1} W[o][k]*x1[k][r] + sum_{k<K2} W[o][K1+k]*x2[k][r]
template<int OUT, int K1, int K2>
__device__ __forceinline__ void matvec_s2(const float* __restrict__ W,
                                          float (*x1)[R], float (*x2)[R],
                                          float (*y)[R], int g, int r)
{
  constexpr int J = OUT / G;
  constexpr int K = K1 + K2;
  float acc[J];
#pragma unroll
  for (int j = 0; j < J; ++j) acc[j] = 0.f;
#pragma unroll 1
  for (int k = 0; k < K1; k += 4) {
    float xv[4];
#pragma unroll
    for (int kk = 0; kk < 4; ++kk) xv[kk] = x1[k + kk][r];
#pragma unroll
    for (int j = 0; j < J; ++j) {
      const int o = g + G * j;
      const float4 w = __ldg(reinterpret_cast<const float4*>(W + (size_t)o * K + k));
      acc[j] = fmaf(w.x, xv[0], acc[j]);
      acc[j] = fmaf(w.y, xv[1], acc[j]);
      acc[j] = fmaf(w.z, xv[2], acc[j]);
      acc[j] = fmaf(w.w, xv[3], acc[j]);
    }
  }
#pragma unroll 1
  for (int k = 0; k < K2; k += 4) {
    float xv[4];
#pragma unroll
    for (int kk = 0; kk < 4; ++kk) xv[kk] = x2[k + kk][r];
#pragma unroll
    for (int j = 0; j < J; ++j) {
      const int o = g + G * j;
      const float4 w = __ldg(reinterpret_cast<const float4*>(W + (size_t)o * K + K1 + k));
      acc[j] = fmaf(w.x, xv[0], acc[j]);
      acc[j] = fmaf(w.y, xv[1], acc[j]);
      acc[j] = fmaf(w.z, xv[2], acc[j]);
      acc[j] = fmaf(w.w, xv[3], acc[j]);
    }
  }
#pragma unroll
  for (int j = 0; j < J; ++j) y[g + G * j][r] = acc[j];
}

// v[i][o][r] = sigmoid(Wg[o]·so + bg[o]) * sum_h Wvo[o][h] * vh[i][h][r]
template<int OUT, int H, int KG>
__device__ __forceinline__ void gated_outv(const float* __restrict__ Wvo,
                                           const float* __restrict__ Wg,
                                           const float* __restrict__ bg,
                                           float (*vh)[256][R],
                                           float (*so)[R],
                                           float (*v)[256][R],
                                           int g, int r)
{
  constexpr int J = OUT / G;
  float gacc[J];
#pragma unroll
  for (int j = 0; j < J; ++j) gacc[j] = 0.f;
#pragma unroll 1
  for (int k = 0; k < KG; k += 4) {
    float xv[4];
#pragma unroll
    for (int kk = 0; kk < 4; ++kk) xv[kk] = so[k + kk][r];
#pragma unroll
    for (int j = 0; j < J; ++j) {
      const int o = g + G * j;
      const float4 w = __ldg(reinterpret_cast<const float4*>(Wg + (size_t)o * KG + k));
      gacc[j] = fmaf(w.x, xv[0], gacc[j]);
      gacc[j] = fmaf(w.y, xv[1], gacc[j]);
      gacc[j] = fmaf(w.z, xv[2], gacc[j]);
      gacc[j] = fmaf(w.w, xv[3], gacc[j]);
    }
  }
  float gate[J];
#pragma unroll
  for (int j = 0; j < J; ++j) {
    const float z = gacc[j] + __ldg(&bg[g + G * j]);
    gate[j] = 1.f / (1.f + __expf(-z));
  }
  float acc[J][3];
#pragma unroll
  for (int j = 0; j < J; ++j) { acc[j][0] = 0.f; acc[j][1] = 0.f; acc[j][2] = 0.f; }
#pragma unroll 1
  for (int h = 0; h < H; h += 4) {
    float xv[3][4];
#pragma unroll
    for (int cc = 0; cc < 4; ++cc) {
      xv[0][cc] = vh[0][h + cc][r];
      xv[1][cc] = vh[1][h + cc][r];
      xv[2][cc] = vh[2][h + cc][r];
    }
#pragma unroll
    for (int j = 0; j < J; ++j) {
      const int o = g + G * j;
      const float4 w = __ldg(reinterpret_cast<const float4*>(Wvo + (size_t)o * H + h));
      acc[j][0] = fmaf(w.x, xv[0][0], acc[j][0]);
      acc[j][1] = fmaf(w.x, xv[1][0], acc[j][1]);
      acc[j][2] = fmaf(w.x, xv[2][0], acc[j][2]);
      acc[j][0] = fmaf(w.y, xv[0][1], acc[j][0]);
      acc[j][1] = fmaf(w.y, xv[1][1], acc[j][1]);
      acc[j][2] = fmaf(w.y, xv[2][1], acc[j][2]);
      acc[j][0] = fmaf(w.z, xv[0][2], acc[j][0]);
      acc[j][1] = fmaf(w.z, xv[1][2], acc[j][1]);
      acc[j][2] = fmaf(w.z, xv[2][2], acc[j][2]);
      acc[j][0] = fmaf(w.w, xv[0][3], acc[j][0]);
      acc[j][1] = fmaf(w.w, xv[1][3], acc[j][1]);
      acc[j][2] = fmaf(w.w, xv[2][3], acc[j][2]);
    }
  }
#pragma unroll
  for (int j = 0; j < J; ++j) {
    const int o = g + G * j;
    v[0][o][r] = gate[j] * acc[j][0];
    v[1][o][r] = gate[j] * acc[j][1];
    v[2][o][r] = gate[j] * acc[j][2];
  }
}

// dst[o][r] = leaky(so[o][r], 0.01) (or plain copy)
template<int OUT, bool LEAKY>
__device__ __forceinline__ void scalar_act(float (*so)[R], float (*dst)[R], int g, int r)
{
  constexpr int J = OUT / G;
#pragma unroll
  for (int j = 0; j < J; ++j) {
    const int o = g + G * j;
    const float vv = so[o][r];
    dst[o][r] = LEAKY ? (vv >= 0.f ? vv : 0.01f * vv) : vv;
  }
}

// vn_leaky_relu elementwise: x <- 0.2x + 0.8*(dot>=0 ? x : x - dot/(dsq+eps)*d)
template<int OUT>
__device__ __forceinline__ void vnleaky_ew(float (*x)[256][R], float (*d)[256][R], int g, int r)
{
  constexpr int J = OUT / G;
#pragma unroll
  for (int j = 0; j < J; ++j) {
    const int o = g + G * j;
    const float x0 = x[0][o][r], x1 = x[1][o][r], x2 = x[2][o][r];
    const float d0 = d[0][o][r], d1 = d[1][o][r], d2 = d[2][o][r];
    const float dot = x0 * d0 + x1 * d1 + x2 * d2;
    const float dsq = d0 * d0 + d1 * d1 + d2 * d2;
    const float t = dot / (dsq + 1e-6f);
    const bool pos = (dot >= 0.f);
    const float n0 = pos ? x0 : (x0 - t * d0);
    const float n1 = pos ? x1 : (x1 - t * d1);
    const float n2 = pos ? x2 : (x2 - t * d2);
    x[0][o][r] = 0.2f * x0 + 0.8f * n0;
    x[1][o][r] = 0.2f * x1 + 0.8f * n1;
    x[2][o][r] = 0.2f * x2 + 0.8f * n2;
  }
}

__global__ __launch_bounds__(NT, 1)
void pe_kernel(const float* __restrict__ h_sca, const float* __restrict__ h_vec,
               const float* __restrict__ pos_compose, const float* __restrict__ pos,
               const float* __restrict__ g1_Wvh, const float* __restrict__ g1_Ws,
               const float* __restrict__ g1_Wvo, const float* __restrict__ g1_Wg,
               const float* __restrict__ g1_bg,  const float* __restrict__ g1_Wd,
               const float* __restrict__ g2_Wvh, const float* __restrict__ g2_Ws,
               const float* __restrict__ g2_Wvo, const float* __restrict__ g2_Wg,
               const float* __restrict__ g2_bg,
               const float* __restrict__ a1_Wvh, const float* __restrict__ a1_Ws,
               const float* __restrict__ a1_Wvo, const float* __restrict__ a1_Wg,
               const float* __restrict__ a1_bg,  const float* __restrict__ a1_Wd,
               const float* __restrict__ a2_Wvh, const float* __restrict__ a2_Ws,
               const float* __restrict__ a2_Wvo, const float* __restrict__ a2_Wg,
               const float* __restrict__ a2_bg,  const float* __restrict__ a2_Wd,
               const float* __restrict__ f_Wvh,  const float* __restrict__ f_Ws,
               const int* __restrict__ idx_focal,
               float* __restrict__ out, int F)
{
  extern __shared__ char smraw[];
  SM& S = *reinterpret_cast<SM*>(smraw);
  const int tid = threadIdx.x;
  const int g = tid >> 4;    // channel group 0..15
  const int r = tid & 15;    // row lane     0..15
  const int row0 = blockIdx.x * R;

  // ---- gather indices ----
  if (tid < R) {
    const int row = row0 + tid;
    S.nidx[tid] = (row < F) ? idx_focal[row] : 0;
  }
  __syncthreads();

  // ---- relpos ----
  if (tid < 3 * R) {
    const int rr = tid / 3, i = tid % 3;
    const int row = row0 + rr;
    const int n = S.nidx[rr];
    const float p = (row < F) ? pos[(size_t)row * 3 + i] : 0.f;
    S.rp[i][rr] = p - pos_compose[(size_t)n * 3 + i];
  }

  // ---- gather h_sca (256/row) and h_vec (64x3/row) ----
  for (int rr = 0; rr < R; ++rr) {
    const size_t n = (size_t)S.nidx[rr];
    S.ssc[tid][rr] = __ldg(&h_sca[n * 256 + tid]);
    if (tid < 192) S.sv[tid % 3][tid / 3][rr] = __ldg(&h_vec[n * 192 + tid]);
  }
  __syncthreads();

  // ================= g1: gv_perceptron =================
  matvec_v<128, 64, true>(g1_Wvh, S.sv, S.sh, S.snorm, g, r);
  __syncthreads();
  matvec_s2<128, 128, 256>(g1_Ws, S.snorm, S.ssc, S.so, g, r);
  __syncthreads();
  gated_outv<128, 128, 128>(g1_Wvo, g1_Wg, g1_bg, S.sh, S.so, S.sv, g, r);
  scalar_act<128, true>(S.so, S.ssc, g, r);
  __syncthreads();
  matvec_v<128, 128, false>(g1_Wd, S.sv, S.sh, S.snorm, g, r);
  __syncthreads();
  vnleaky_ew<128>(S.sv, S.sh, g, r);
  __syncthreads();

  // ================= g2: gv_linear =================
  matvec_v<128, 128, true>(g2_Wvh, S.sv, S.sh, S.snorm, g, r);
  __syncthreads();
  matvec_s2<128, 128, 128>(g2_Ws, S.snorm, S.ssc, S.so, g, r);
  __syncthreads();
  gated_outv<128, 128, 128>(g2_Wvo, g2_Wg, g2_bg, S.sh, S.so, S.sv, g, r);
  scalar_act<128, false>(S.so, S.ssc, g, r);   // no activation (raw out_s)
  __syncthreads();

  // ================= a1: gv_perceptron =================
  matvec_v<256, 128, true>(a1_Wvh, S.sv, S.sh, S.snorm, g, r);
  __syncthreads();
  matvec_s2<128, 256, 128>(a1_Ws, S.snorm, S.ssc, S.so, g, r);
  __syncthreads();
  gated_outv<256, 256, 128>(a1_Wvo, a1_Wg, a1_bg, S.sh, S.so, S.sv, g, r);
  scalar_act<128, true>(S.so, S.ssc, g, r);
  __syncthreads();
  matvec_v<256, 256, false>(a1_Wd, S.sv, S.sh, S.snorm, g, r);
  __syncthreads();
  vnleaky_ew<256>(S.sv, S.sh, g, r);
  __syncthreads();

  // ================= split: inner = <x_vec2, relpos> -> ssc[128..255] =================
  {
    const float rp0 = S.rp[0][r], rp1 = S.rp[1][r], rp2 = S.rp[2][r];
#pragma unroll
    for (int j = 0; j < 8; ++j) {
      const int o = g + G * j;
      const float in_ = S.sv[0][128 + o][r] * rp0
                      + S.sv[1][128 + o][r] * rp1
                      + S.sv[2][128 + o][r] * rp2;
      S.ssc[128 + o][r] = in_;
    }
  }
  __syncthreads();

  // ================= a2: gv_perceptron (on x_vec = sv[0..127]) =================
  matvec_v<128, 128, true>(a2_Wvh, S.sv, S.sh, S.snorm, g, r);
  __syncthreads();
  matvec_s2<128, 128, 256>(a2_Ws, S.snorm, S.ssc, S.so, g, r);
  __syncthreads();
  gated_outv<128, 128, 128>(a2_Wvo, a2_Wg, a2_bg, S.sh, S.so, S.sv, g, r);
  scalar_act<128, true>(S.so, S.ssc, g, r);
  __syncthreads();
  matvec_v<128, 128, false>(a2_Wd, S.sv, S.sh, S.snorm, g, r);
  __syncthreads();
  vnleaky_ew<128>(S.sv, S.sh, g, r);
  __syncthreads();

  // ================= final: out = [||f_Wvh@v||, s3] @ f_Ws^T =================
  matvec_v<128, 128, true>(f_Wvh, S.sv, S.sh, S.snorm, g, r);
  __syncthreads();
  {
    // each group sums 16 consecutive k of the 256-long dot, then reduce over groups
    float acc = 0.f;
#pragma unroll
    for (int kk = 0; kk < 16; ++kk) {
      const int k = g * 16 + kk;
      const float xv = (k < 128) ? S.snorm[k][r] : S.ssc[k - 128][r];
      acc = fmaf(__ldg(&f_Ws[k]), xv, acc);
    }
    S.so[g][r] = acc;
  }
  __syncthreads();
  if (tid < R) {
    const int row = row0 + tid;
    float acc = 0.f;
#pragma unroll
    for (int gg = 0; gg < G; ++gg) acc += S.so[gg][tid];
    if (row < F) out[row] = acc;
  }
}

extern "C" void kernel_launch(void* const* d_in, const int* in_sizes, int n_in,
                              void* d_out, int out_size)
{
  const float* h_sca       = (const float*)d_in[0];
  const float* h_vec       = (const float*)d_in[1];
  const float* pos_compose = (const float*)d_in[2];
  const float* pos         = (const float*)d_in[3];
  const float* g1_Wvh = (const float*)d_in[4];
  const float* g1_Ws  = (const float*)d_in[5];
  const float* g1_Wvo = (const float*)d_in[6];
  const float* g1_Wg  = (const float*)d_in[7];
  const float* g1_bg  = (const float*)d_in[8];
  const float* g1_Wd  = (const float*)d_in[9];
  const float* g2_Wvh = (const float*)d_in[10];
  const float* g2_Ws  = (const float*)d_in[11];
  const float* g2_Wvo = (const float*)d_in[12];
  const float* g2_Wg  = (const float*)d_in[13];
  const float* g2_bg  = (const float*)d_in[14];
  const float* a1_Wvh = (const float*)d_in[15];
  const float* a1_Ws  = (const float*)d_in[16];
  const float* a1_Wvo = (const float*)d_in[17];
  const float* a1_Wg  = (const float*)d_in[18];
  const float* a1_bg  = (const float*)d_in[19];
  const float* a1_Wd  = (const float*)d_in[20];
  const float* a2_Wvh = (const float*)d_in[21];
  const float* a2_Ws  = (const float*)d_in[22];
  const float* a2_Wvo = (const float*)d_in[23];
  const float* a2_Wg  = (const float*)d_in[24];
  const float* a2_bg  = (const float*)d_in[25];
  const float* a2_Wd  = (const float*)d_in[26];
  const float* f_Wvh  = (const float*)d_in[27];
  const float* f_Ws   = (const float*)d_in[28];
  const int*   idx_focal = (const int*)d_in[29];

  const int F = in_sizes[3] / 3;   // pos is (F, 3)
  const int grid = (F + R - 1) / R;

  cudaFuncSetAttribute(pe_kernel, cudaFuncAttributeMaxDynamicSharedMemorySize,
                       (int)sizeof(SM));

  pe_kernel<<<grid, NT, sizeof(SM)>>>(
      h_sca, h_vec, pos_compose, pos,
      g1_Wvh, g1_Ws, g1_Wvo, g1_Wg, g1_bg, g1_Wd,
      g2_Wvh, g2_Ws, g2_Wvo, g2_Wg, g2_bg,
      a1_Wvh, a1_Ws, a1_Wvo, a1_Wg, a1_bg, a1_Wd,
      a2_Wvh, a2_Ws, a2_Wvo, a2_Wg, a2_bg, a2_Wd,
      f_Wvh, f_Ws, idx_focal,
      (float*)d_out, F);
}

// round 3
// speedup vs baseline: 1.2513x; 1.2513x over previous
#include <cuda_runtime.h>
#include <math.h>

// ---------------------------------------------------------------------------
// PositionEvaluator, round 2: packed f32x2 (FFMA2) row-pair version.
// One CTA processes R=16 focal rows; each thread handles a ROW PAIR packed
// into 64-bit f32x2 lanes -> FMA-pipe instruction count halves vs round 1.
// Thread map: p = tid & 7 (row pair 0..7), g = tid >> 3 (channel group 0..31).
// Activations in smem transposed [channel][row] (row fast, pairs 8B aligned).
// ---------------------------------------------------------------------------

#define R  16          // rows per CTA
#define P  8           // row pairs per CTA
#define G  32          // channel groups
#define NT 256

typedef unsigned long long u64;
union F2 { u64 u; float2 f; };

__device__ __forceinline__ u64 ffma2(u64 a, u64 b, u64 c) {
  u64 d; asm("fma.rn.f32x2 %0, %1, %2, %3;" : "=l"(d) : "l"(a), "l"(b), "l"(c)); return d;
}
__device__ __forceinline__ u64 fmul2(u64 a, u64 b) {
  u64 d; asm("mul.rn.f32x2 %0, %1, %2;" : "=l"(d) : "l"(a), "l"(b)); return d;
}
__device__ __forceinline__ u64 dup2(float w) {
  u64 d; asm("mov.b64 %0, {%1, %1};" : "=l"(d) : "f"(w)); return d;
}
__device__ __forceinline__ u64 ld2(const float* p) {
  return *reinterpret_cast<const u64*>(p);
}
__device__ __forceinline__ void st2(float* p, u64 v) {
  *reinterpret_cast<u64*>(p) = v;
}

struct SM {
  float sv[3][256][R];    // current vector activations (comp, channel, row)
  float sh[3][256][R];    // vh / d scratch
  float snorm[256][R];    // ||vh|| per channel
  float ssc[256][R];      // scalar activations
  float so[128][R];       // out_s / final reduce scratch (first 32 rows used at end)
  float rp[3][R];         // relpos
  int   nidx[R];
};

// y[i][o][pair] = sum_c W[o][c] * x[i][c][pair];  optionally nrm = ||y||
template<int OUT, int CIN, bool NORM>
__device__ __forceinline__ void matvec_v(const float* __restrict__ W,
                                         float (*x)[256][R],
                                         float (*y)[256][R],
                                         float (*nrm)[R],
                                         int g, int p)
{
  constexpr int J = OUT / G;
  u64 acc[J][3];
#pragma unroll
  for (int j = 0; j < J; ++j) { acc[j][0] = 0ull; acc[j][1] = 0ull; acc[j][2] = 0ull; }
#pragma unroll 1
  for (int c = 0; c < CIN; c += 4) {
    u64 xv[3][4];
#pragma unroll
    for (int cc = 0; cc < 4; ++cc) {
      xv[0][cc] = ld2(&x[0][c + cc][2 * p]);
      xv[1][cc] = ld2(&x[1][c + cc][2 * p]);
      xv[2][cc] = ld2(&x[2][c + cc][2 * p]);
    }
#pragma unroll
    for (int j = 0; j < J; ++j) {
      const int o = g + G * j;
      const float4 w = __ldg(reinterpret_cast<const float4*>(W + (size_t)o * CIN + c));
      const u64 w0 = dup2(w.x), w1 = dup2(w.y), w2 = dup2(w.z), w3 = dup2(w.w);
#pragma unroll
      for (int i = 0; i < 3; ++i) {
        acc[j][i] = ffma2(w0, xv[i][0], acc[j][i]);
        acc[j][i] = ffma2(w1, xv[i][1], acc[j][i]);
        acc[j][i] = ffma2(w2, xv[i][2], acc[j][i]);
        acc[j][i] = ffma2(w3, xv[i][3], acc[j][i]);
      }
    }
  }
#pragma unroll
  for (int j = 0; j < J; ++j) {
    const int o = g + G * j;
    st2(&y[0][o][2 * p], acc[j][0]);
    st2(&y[1][o][2 * p], acc[j][1]);
    st2(&y[2][o][2 * p], acc[j][2]);
    if (NORM) {
      u64 s = fmul2(acc[j][0], acc[j][0]);
      s = ffma2(acc[j][1], acc[j][1], s);
      s = ffma2(acc[j][2], acc[j][2], s);
      F2 t; t.u = s;
      F2 n; n.f.x = sqrtf(t.f.x); n.f.y = sqrtf(t.f.y);
      st2(&nrm[o][2 * p], n.u);
    }
  }
}

// y[o][pair] = sum_{k<K1} W[o][k]*x1[k][pair] + sum_{k<K2} W[o][K1+k]*x2[k][pair]
template<int OUT, int K1, int K2>
__device__ __forceinline__ void matvec_s2(const float* __restrict__ W,
                                          float (*x1)[R], float (*x2)[R],
                                          float (*y)[R], int g, int p)
{
  constexpr int J = OUT / G;
  constexpr int K = K1 + K2;
  u64 acc[J];
#pragma unroll
  for (int j = 0; j < J; ++j) acc[j] = 0ull;
#pragma unroll 1
  for (int k = 0; k < K1; k += 4) {
    u64 xv[4];
#pragma unroll
    for (int kk = 0; kk < 4; ++kk) xv[kk] = ld2(&x1[k + kk][2 * p]);
#pragma unroll
    for (int j = 0; j < J; ++j) {
      const int o = g + G * j;
      const float4 w = __ldg(reinterpret_cast<const float4*>(W + (size_t)o * K + k));
      acc[j] = ffma2(dup2(w.x), xv[0], acc[j]);
      acc[j] = ffma2(dup2(w.y), xv[1], acc[j]);
      acc[j] = ffma2(dup2(w.z), xv[2], acc[j]);
      acc[j] = ffma2(dup2(w.w), xv[3], acc[j]);
    }
  }
#pragma unroll 1
  for (int k = 0; k < K2; k += 4) {
    u64 xv[4];
#pragma unroll
    for (int kk = 0; kk < 4; ++kk) xv[kk] = ld2(&x2[k + kk][2 * p]);
#pragma unroll
    for (int j = 0; j < J; ++j) {
      const int o = g + G * j;
      const float4 w = __ldg(reinterpret_cast<const float4*>(W + (size_t)o * K + K1 + k));
      acc[j] = ffma2(dup2(w.x), xv[0], acc[j]);
      acc[j] = ffma2(dup2(w.y), xv[1], acc[j]);
      acc[j] = ffma2(dup2(w.z), xv[2], acc[j]);
      acc[j] = ffma2(dup2(w.w), xv[3], acc[j]);
    }
  }
#pragma unroll
  for (int j = 0; j < J; ++j) st2(&y[g + G * j][2 * p], acc[j]);
}

// v[i][o][pair] = sigmoid(Wg[o]·so + bg[o]) * sum_h Wvo[o][h] * vh[i][h][pair]
template<int OUT, int H, int KG>
__device__ __forceinline__ void gated_outv(const float* __restrict__ Wvo,
                                           const float* __restrict__ Wg,
                                           const float* __restrict__ bg,
                                           float (*vh)[256][R],
                                           float (*so)[R],
                                           float (*v)[256][R],
                                           int g, int p)
{
  constexpr int J = OUT / G;
  u64 gacc[J];
#pragma unroll
  for (int j = 0; j < J; ++j) gacc[j] = 0ull;
#pragma unroll 1
  for (int k = 0; k < KG; k += 4) {
    u64 xv[4];
#pragma unroll
    for (int kk = 0; kk < 4; ++kk) xv[kk] = ld2(&so[k + kk][2 * p]);
#pragma unroll
    for (int j = 0; j < J; ++j) {
      const int o = g + G * j;
      const float4 w = __ldg(reinterpret_cast<const float4*>(Wg + (size_t)o * KG + k));
      gacc[j] = ffma2(dup2(w.x), xv[0], gacc[j]);
      gacc[j] = ffma2(dup2(w.y), xv[1], gacc[j]);
      gacc[j] = ffma2(dup2(w.z), xv[2], gacc[j]);
      gacc[j] = ffma2(dup2(w.w), xv[3], gacc[j]);
    }
  }
  u64 gate[J];
#pragma unroll
  for (int j = 0; j < J; ++j) {
    const float b = __ldg(&bg[g + G * j]);
    F2 t; t.u = gacc[j];
    F2 gt;
    gt.f.x = 1.f / (1.f + __expf(-(t.f.x + b)));
    gt.f.y = 1.f / (1.f + __expf(-(t.f.y + b)));
    gate[j] = gt.u;
  }
  u64 acc[J][3];
#pragma unroll
  for (int j = 0; j < J; ++j) { acc[j][0] = 0ull; acc[j][1] = 0ull; acc[j][2] = 0ull; }
#pragma unroll 1
  for (int h = 0; h < H; h += 4) {
    u64 xv[3][4];
#pragma unroll
    for (int cc = 0; cc < 4; ++cc) {
      xv[0][cc] = ld2(&vh[0][h + cc][2 * p]);
      xv[1][cc] = ld2(&vh[1][h + cc][2 * p]);
      xv[2][cc] = ld2(&vh[2][h + cc][2 * p]);
    }
#pragma unroll
    for (int j = 0; j < J; ++j) {
      const int o = g + G * j;
      const float4 w = __ldg(reinterpret_cast<const float4*>(Wvo + (size_t)o * H + h));
      const u64 w0 = dup2(w.x), w1 = dup2(w.y), w2 = dup2(w.z), w3 = dup2(w.w);
#pragma unroll
      for (int i = 0; i < 3; ++i) {
        acc[j][i] = ffma2(w0, xv[i][0], acc[j][i]);
        acc[j][i] = ffma2(w1, xv[i][1], acc[j][i]);
        acc[j][i] = ffma2(w2, xv[i][2], acc[j][i]);
        acc[j][i] = ffma2(w3, xv[i][3], acc[j][i]);
      }
    }
  }
#pragma unroll
  for (int j = 0; j < J; ++j) {
    const int o = g + G * j;
    st2(&v[0][o][2 * p], fmul2(gate[j], acc[j][0]));
    st2(&v[1][o][2 * p], fmul2(gate[j], acc[j][1]));
    st2(&v[2][o][2 * p], fmul2(gate[j], acc[j][2]));
  }
}

template<int OUT, bool LEAKY>
__device__ __forceinline__ void scalar_act(float (*so)[R], float (*dst)[R], int g, int p)
{
  constexpr int J = OUT / G;
#pragma unroll
  for (int j = 0; j < J; ++j) {
    const int o = g + G * j;
    F2 t; t.u = ld2(&so[o][2 * p]);
    if (LEAKY) {
      t.f.x = t.f.x >= 0.f ? t.f.x : 0.01f * t.f.x;
      t.f.y = t.f.y >= 0.f ? t.f.y : 0.01f * t.f.y;
    }
    st2(&dst[o][2 * p], t.u);
  }
}

template<int OUT>
__device__ __forceinline__ void vnleaky_ew(float (*x)[256][R], float (*d)[256][R], int g, int p)
{
  constexpr int J = OUT / G;
#pragma unroll
  for (int j = 0; j < J; ++j) {
    const int o = g + G * j;
    F2 x0, x1, x2, d0, d1, d2;
    x0.u = ld2(&x[0][o][2 * p]); x1.u = ld2(&x[1][o][2 * p]); x2.u = ld2(&x[2][o][2 * p]);
    d0.u = ld2(&d[0][o][2 * p]); d1.u = ld2(&d[1][o][2 * p]); d2.u = ld2(&d[2][o][2 * p]);
    u64 dotu = fmul2(x0.u, d0.u); dotu = ffma2(x1.u, d1.u, dotu); dotu = ffma2(x2.u, d2.u, dotu);
    u64 dsqu = fmul2(d0.u, d0.u); dsqu = ffma2(d1.u, d1.u, dsqu); dsqu = ffma2(d2.u, d2.u, dsqu);
    F2 dot, dsq; dot.u = dotu; dsq.u = dsqu;
    F2 o0, o1, o2;
#pragma unroll
    for (int h = 0; h < 2; ++h) {
      const float dt = h ? dot.f.y : dot.f.x;
      const float ds = h ? dsq.f.y : dsq.f.x;
      const float xa = h ? x0.f.y : x0.f.x;
      const float xb = h ? x1.f.y : x1.f.x;
      const float xc = h ? x2.f.y : x2.f.x;
      const float da = h ? d0.f.y : d0.f.x;
      const float db = h ? d1.f.y : d1.f.x;
      const float dc = h ? d2.f.y : d2.f.x;
      const float t = dt / (ds + 1e-6f);
      const bool pos = (dt >= 0.f);
      const float na = pos ? xa : (xa - t * da);
      const float nb = pos ? xb : (xb - t * db);
      const float nc = pos ? xc : (xc - t * dc);
      const float ra = 0.2f * xa + 0.8f * na;
      const float rb = 0.2f * xb + 0.8f * nb;
      const float rc = 0.2f * xc + 0.8f * nc;
      if (h) { o0.f.y = ra; o1.f.y = rb; o2.f.y = rc; }
      else   { o0.f.x = ra; o1.f.x = rb; o2.f.x = rc; }
    }
    st2(&x[0][o][2 * p], o0.u);
    st2(&x[1][o][2 * p], o1.u);
    st2(&x[2][o][2 * p], o2.u);
  }
}

__global__ __launch_bounds__(NT, 1)
void pe_kernel(const float* __restrict__ h_sca, const float* __restrict__ h_vec,
               const float* __restrict__ pos_compose, const float* __restrict__ pos,
               const float* __restrict__ g1_Wvh, const float* __restrict__ g1_Ws,
               const float* __restrict__ g1_Wvo, const float* __restrict__ g1_Wg,
               const float* __restrict__ g1_bg,  const float* __restrict__ g1_Wd,
               const float* __restrict__ g2_Wvh, const float* __restrict__ g2_Ws,
               const float* __restrict__ g2_Wvo, const float* __restrict__ g2_Wg,
               const float* __restrict__ g2_bg,
               const float* __restrict__ a1_Wvh, const float* __restrict__ a1_Ws,
               const float* __restrict__ a1_Wvo, const float* __restrict__ a1_Wg,
               const float* __restrict__ a1_bg,  const float* __restrict__ a1_Wd,
               const float* __restrict__ a2_Wvh, const float* __restrict__ a2_Ws,
               const float* __restrict__ a2_Wvo, const float* __restrict__ a2_Wg,
               const float* __restrict__ a2_bg,  const float* __restrict__ a2_Wd,
               const float* __restrict__ f_Wvh,  const float* __restrict__ f_Ws,
               const int* __restrict__ idx_focal,
               float* __restrict__ out, int F)
{
  extern __shared__ char smraw[];
  SM& S = *reinterpret_cast<SM*>(smraw);
  const int tid = threadIdx.x;
  const int g = tid >> 3;    // channel group 0..31
  const int p = tid & 7;     // row pair     0..7
  const int row0 = blockIdx.x * R;

  if (tid < R) {
    const int row = row0 + tid;
    S.nidx[tid] = (row < F) ? idx_focal[row] : 0;
  }
  __syncthreads();

  if (tid < 3 * R) {
    const int rr = tid / 3, i = tid % 3;
    const int row = row0 + rr;
    const int n = S.nidx[rr];
    const float pv = (row < F) ? pos[(size_t)row * 3 + i] : 0.f;
    S.rp[i][rr] = pv - pos_compose[(size_t)n * 3 + i];
  }

  for (int rr = 0; rr < R; ++rr) {
    const size_t n = (size_t)S.nidx[rr];
    S.ssc[tid][rr] = __ldg(&h_sca[n * 256 + tid]);
    if (tid < 192) S.sv[tid % 3][tid / 3][rr] = __ldg(&h_vec[n * 192 + tid]);
  }
  __syncthreads();

  // ================= g1: gv_perceptron =================
  matvec_v<128, 64, true>(g1_Wvh, S.sv, S.sh, S.snorm, g, p);
  __syncthreads();
  matvec_s2<128, 128, 256>(g1_Ws, S.snorm, S.ssc, S.so, g, p);
  __syncthreads();
  gated_outv<128, 128, 128>(g1_Wvo, g1_Wg, g1_bg, S.sh, S.so, S.sv, g, p);
  scalar_act<128, true>(S.so, S.ssc, g, p);
  __syncthreads();
  matvec_v<128, 128, false>(g1_Wd, S.sv, S.sh, S.snorm, g, p);
  __syncthreads();
  vnleaky_ew<128>(S.sv, S.sh, g, p);
  __syncthreads();

  // ================= g2: gv_linear =================
  matvec_v<128, 128, true>(g2_Wvh, S.sv, S.sh, S.snorm, g, p);
  __syncthreads();
  matvec_s2<128, 128, 128>(g2_Ws, S.snorm, S.ssc, S.so, g, p);
  __syncthreads();
  gated_outv<128, 128, 128>(g2_Wvo, g2_Wg, g2_bg, S.sh, S.so, S.sv, g, p);
  scalar_act<128, false>(S.so, S.ssc, g, p);
  __syncthreads();

  // ================= a1: gv_perceptron =================
  matvec_v<256, 128, true>(a1_Wvh, S.sv, S.sh, S.snorm, g, p);
  __syncthreads();
  matvec_s2<128, 256, 128>(a1_Ws, S.snorm, S.ssc, S.so, g, p);
  __syncthreads();
  gated_outv<256, 256, 128>(a1_Wvo, a1_Wg, a1_bg, S.sh, S.so, S.sv, g, p);
  scalar_act<128, true>(S.so, S.ssc, g, p);
  __syncthreads();
  matvec_v<256, 256, false>(a1_Wd, S.sv, S.sh, S.snorm, g, p);
  __syncthreads();
  vnleaky_ew<256>(S.sv, S.sh, g, p);
  __syncthreads();

  // ===== split: inner = <x_vec2, relpos> -> ssc[128..255] =====
  {
    const u64 rp0 = ld2(&S.rp[0][2 * p]);
    const u64 rp1 = ld2(&S.rp[1][2 * p]);
    const u64 rp2 = ld2(&S.rp[2][2 * p]);
#pragma unroll
    for (int j = 0; j < 4; ++j) {
      const int o = g + G * j;
      u64 acc = fmul2(ld2(&S.sv[0][128 + o][2 * p]), rp0);
      acc = ffma2(ld2(&S.sv[1][128 + o][2 * p]), rp1, acc);
      acc = ffma2(ld2(&S.sv[2][128 + o][2 * p]), rp2, acc);
      st2(&S.ssc[128 + o][2 * p], acc);
    }
  }
  __syncthreads();

  // ================= a2: gv_perceptron (on x_vec = sv[0..127]) =================
  matvec_v<128, 128, true>(a2_Wvh, S.sv, S.sh, S.snorm, g, p);
  __syncthreads();
  matvec_s2<128, 128, 256>(a2_Ws, S.snorm, S.ssc, S.so, g, p);
  __syncthreads();
  gated_outv<128, 128, 128>(a2_Wvo, a2_Wg, a2_bg, S.sh, S.so, S.sv, g, p);
  scalar_act<128, true>(S.so, S.ssc, g, p);
  __syncthreads();
  matvec_v<128, 128, false>(a2_Wd, S.sv, S.sh, S.snorm, g, p);
  __syncthreads();
  vnleaky_ew<128>(S.sv, S.sh, g, p);
  __syncthreads();

  // ================= final: out = [||f_Wvh@v||, s3] @ f_Ws^T =================
  matvec_v<128, 128, true>(f_Wvh, S.sv, S.sh, S.snorm, g, p);
  __syncthreads();
  {
    u64 acc = 0ull;
#pragma unroll
    for (int kk = 0; kk < 8; ++kk) {
      const int k = g * 8 + kk;
      const u64 xv = (k < 128) ? ld2(&S.snorm[k][2 * p]) : ld2(&S.ssc[k - 128][2 * p]);
      acc = ffma2(dup2(__ldg(&f_Ws[k])), xv, acc);
    }
    st2(&S.so[g][2 * p], acc);
  }
  __syncthreads();
  if (tid < R) {
    const int row = row0 + tid;
    float acc = 0.f;
#pragma unroll
    for (int gg = 0; gg < G; ++gg) acc += S.so[gg][tid];
    if (row < F) out[row] = acc;
  }
}

extern "C" void kernel_launch(void* const* d_in, const int* in_sizes, int n_in,
                              void* d_out, int out_size)
{
  const float* h_sca       = (const float*)d_in[0];
  const float* h_vec       = (const float*)d_in[1];
  const float* pos_compose = (const float*)d_in[2];
  const float* pos         = (const float*)d_in[3];
  const float* g1_Wvh = (const float*)d_in[4];
  const float* g1_Ws  = (const float*)d_in[5];
  const float* g1_Wvo = (const float*)d_in[6];
  const float* g1_Wg  = (const float*)d_in[7];
  const float* g1_bg  = (const float*)d_in[8];
  const float* g1_Wd  = (const float*)d_in[9];
  const float* g2_Wvh = (const float*)d_in[10];
  const float* g2_Ws  = (const float*)d_in[11];
  const float* g2_Wvo = (const float*)d_in[12];
  const float* g2_Wg  = (const float*)d_in[13];
  const float* g2_bg  = (const float*)d_in[14];
  const float* a1_Wvh = (const float*)d_in[15];
  const float* a1_Ws  = (const float*)d_in[16];
  const float* a1_Wvo = (const float*)d_in[17];
  const float* a1_Wg  = (const float*)d_in[18];
  const float* a1_bg  = (const float*)d_in[19];
  const float* a1_Wd  = (const float*)d_in[20];
  const float* a2_Wvh = (const float*)d_in[21];
  const float* a2_Ws  = (const float*)d_in[22];
  const float* a2_Wvo = (const float*)d_in[23];
  const float* a2_Wg  = (const float*)d_in[24];
  const float* a2_bg  = (const float*)d_in[25];
  const float* a2_Wd  = (const float*)d_in[26];
  const float* f_Wvh  = (const float*)d_in[27];
  const float* f_Ws   = (const float*)d_in[28];
  const int*   idx_focal = (const int*)d_in[29];

  const int F = in_sizes[3] / 3;   // pos is (F, 3)
  const int grid = (F + R - 1) / R;

  cudaFuncSetAttribute(pe_kernel, cudaFuncAttributeMaxDynamicSharedMemorySize,
                       (int)sizeof(SM));

  pe_kernel<<<grid, NT, sizeof(SM)>>>(
      h_sca, h_vec, pos_compose, pos,
      g1_Wvh, g1_Ws, g1_Wvo, g1_Wg, g1_bg, g1_Wd,
      g2_Wvh, g2_Ws, g2_Wvo, g2_Wg, g2_bg,
      a1_Wvh, a1_Ws, a1_Wvo, a1_Wg, a1_bg, a1_Wd,
      a2_Wvh, a2_Ws, a2_Wvo, a2_Wg, a2_bg, a2_Wd,
      f_Wvh, f_Ws, idx_focal,
      (float*)d_out, F);
}